// round 12
// baseline (speedup 1.0000x reference)
#include <cuda_runtime.h>
#include <cuda_fp16.h>
#include <cstdint>

#define BSZ    64
#define TLEN   512
#define UDIM   1024
#define KREAL  2048
#define XROWS  32768
#define OMEGA_F 0.006135923151542565f
#define OV     16
#define CLEN   32
#define NSTEP  (CLEN + OV)          // 48
#define SROWS  1024
#define NCTA_SCAN 128
#define NTHR   512
#define NCH    16                    // K chunks of 128

// smem: three stages x (A 32K + B 32K) = 192 KB
// Each operand chunk = two 16KB sub-tiles (k-halves), each 128 rows x 128 B.
#define TBH     16384
#define STB     65536
#define SM_A(st) ((st)*STB)
#define SM_B(st) ((st)*STB + 32768)
#define SMEM_DYN 196608
#define CST     132                  // Cs f32 row stride (epilogue overlay)

// ---------------------------------------------------------------------------
// Device scratch (static; no runtime allocation)
// ---------------------------------------------------------------------------
__device__ float2 g_W[(size_t)(TLEN + OV) * BSZ * UDIM];            // fp32 W; slots 0..OV-1 pad (z0 at OV-1)
__device__ __align__(16) __half g_awt[(size_t)KREAL * KREAL];       // A weights [n][k] fp16, x0.5
__device__ __align__(16) __half g_bwt[(size_t)KREAL * KREAL];       // B weights
__device__ __align__(16) __half g_xbf[(size_t)XROWS * KREAL];       // x fp16 [row][k]
__device__ __align__(16) __half g_z[2][(size_t)SROWS * KREAL];      // state double buffer fp16
__device__ unsigned g_bar_cnt, g_bar_phase;

// ---------------------------------------------------------------------------
// Helpers
// ---------------------------------------------------------------------------
#define SWZ(x) ((x) ^ (((x) >> 3) & 0x70))

static __device__ __forceinline__ uint32_t smem_u32(const void* p) {
    uint32_t a;
    asm("{ .reg .u64 t; cvta.to.shared.u64 t, %1; cvt.u32.u64 %0, t; }" : "=r"(a) : "l"(p));
    return a;
}
#define CP16(saddr, gptr) \
    asm volatile("cp.async.cg.shared.global [%0], [%1], 16;" :: "r"(saddr), "l"(gptr))
#define CP_COMMIT() asm volatile("cp.async.commit_group;" ::: "memory")
#define CP_WAIT(n)  asm volatile("cp.async.wait_group %0;" :: "n"(n) : "memory")

static __device__ __forceinline__ void ldsm_x4(uint32_t (&r)[4], uint32_t a) {
    asm volatile("ldmatrix.sync.aligned.m8n8.x4.shared.b16 {%0,%1,%2,%3}, [%4];"
        : "=r"(r[0]), "=r"(r[1]), "=r"(r[2]), "=r"(r[3]) : "r"(a));
}
static __device__ __forceinline__ void mma_fp16(
    float (&d)[4], const uint32_t (&a)[4], uint32_t b0, uint32_t b1)
{
    asm volatile("mma.sync.aligned.m16n8k16.row.col.f32.f16.f16.f32 "
        "{%0,%1,%2,%3}, {%4,%5,%6,%7}, {%8,%9}, {%0,%1,%2,%3};"
        : "+f"(d[0]), "+f"(d[1]), "+f"(d[2]), "+f"(d[3])
        : "r"(a[0]), "r"(a[1]), "r"(a[2]), "r"(a[3]), "r"(b0), "r"(b1));
}
static __device__ __forceinline__ uint32_t pkh(__half a, __half b) {
    return (uint32_t)__half_as_ushort(a) | ((uint32_t)__half_as_ushort(b) << 16);
}

// ---------------------------------------------------------------------------
// Kernel 0a: pack weights (transposed real embedding, 0.5-scaled, fp16),
//            init W pad (z0 at slot OV-1), zero state buf 0
// ---------------------------------------------------------------------------
__global__ __launch_bounds__(256) void pack_tc(
    const float* __restrict__ Ar, const float* __restrict__ Ai,
    const float* __restrict__ Br, const float* __restrict__ Bi,
    const float* __restrict__ z0r, const float* __restrict__ z0i)
{
    int i = blockIdx.x * 256 + threadIdx.x;   // 0 .. 4M-1
    {
        int n = i >> 11, k = i & 2047;
        int kk = k & 1023, nn = n & 1023;
        float a, b;
        if (k < 1024) {
            if (n < 1024) { a = Ar[k*1024 + n];  b = Br[k*1024 + n];  }
            else          { a = Ai[k*1024 + nn]; b = Bi[k*1024 + nn]; }
        } else {
            if (n < 1024) { a = -Ai[kk*1024 + n];  b = -Bi[kk*1024 + n];  }
            else          { a =  Ar[kk*1024 + nn]; b =  Br[kk*1024 + nn]; }
        }
        g_awt[i] = __float2half_rn(0.5f * a);
        g_bwt[i] = __float2half_rn(0.5f * b);
    }
    if (i < OV * BSZ * UDIM) {                // 1.05M: W pad, z0 at slot OV-1
        int slot = i >> 16, r = i & 65535;
        g_W[i] = (slot == OV - 1) ? make_float2(z0r[r], z0i[r]) : make_float2(0.f, 0.f);
    }
    if (i < (int)(SROWS * KREAL / 2))          // 1.05M u32 = state buf 0
        ((uint32_t*)g_z[0])[i] = 0u;
}

// ---------------------------------------------------------------------------
// Kernel 0b: convert x to fp16, k-layout [re(1024) | im(1024)]
// ---------------------------------------------------------------------------
__global__ __launch_bounds__(256) void xhalf(
    const float* __restrict__ xr, const float* __restrict__ xi)
{
    int i = blockIdx.x * 256 + threadIdx.x;
    int row = i >> 9;
    int kq = (i & 511) * 4;
    const float* src = (kq < 1024) ? xr : xi;
    float4 v = *(const float4*)(src + (size_t)row * 1024 + (kq & 1023));
    *(uint2*)(g_xbf + (size_t)row * KREAL + kq) = make_uint2(
        pkh(__float2half_rn(v.x), __float2half_rn(v.y)),
        pkh(__float2half_rn(v.z), __float2half_rn(v.w)));
}

// ---------------------------------------------------------------------------
// GEMM machinery.  512 threads, warp grid 4x4 (each warp 32 rows x 32 cols).
//   A: activations fp16 [row][2048], rows arow0..+127, K chunks of 128
//   B: weights fp16 [n][2048]; smem row j<64 -> n=u0+j (re), j>=64 -> im half
// ---------------------------------------------------------------------------
static __device__ __forceinline__ void load_chunk(
    uint32_t sb, int st, int ci, int tid,
    const __half* a, size_t arow0, const __half* w, int u0)
{
    // A: 128 rows x 128 fp16 (256B/row) = 2048 x 16B transfers, 4/thread
    #pragma unroll
    for (int l = 0; l < 4; l++) {
        int idx = tid + l * NTHR;
        int row = idx >> 4, g16 = idx & 15;
        int kh = g16 >> 3, c16 = g16 & 7;
        CP16(sb + SM_A(st) + kh * TBH + SWZ(row * 128 + c16 * 16),
             a + (arow0 + row) * KREAL + ci * 128 + g16 * 8);
    }
    // B: same shape
    #pragma unroll
    for (int l = 0; l < 4; l++) {
        int idx = tid + l * NTHR;
        int j = idx >> 4, g16 = idx & 15;
        int kh = g16 >> 3, c16 = g16 & 7;
        int n = u0 + j + ((j >= 64) ? 960 : 0);
        CP16(sb + SM_B(st) + kh * TBH + SWZ(j * 128 + c16 * 16),
             w + (size_t)n * KREAL + ci * 128 + g16 * 8);
    }
    CP_COMMIT();
}

static __device__ __forceinline__ void compute_chunk(
    uint32_t sb, int st, int tid, float (&acc)[2][4][4])
{
    int lane = tid & 31, wid = tid >> 5;
    int wr = wid >> 2, wc = wid & 3;
    uint32_t abase = sb + SM_A(st);
    uint32_t bbase = sb + SM_B(st);
    int ar = lane & 15, ac = lane >> 4;
    int br = lane & 7, bc = (lane >> 3) & 1, bt = lane >> 4;

    #pragma unroll
    for (int k16 = 0; k16 < 8; k16++) {
        uint32_t sub = (k16 >> 2) * TBH;
        int kb = (k16 & 3) * 32;
        uint32_t ah[2][4], bh[2][4];
        #pragma unroll
        for (int mt = 0; mt < 2; mt++) {
            uint32_t off = sub + SWZ((wr * 32 + mt * 16 + ar) * 128 + kb + ac * 16);
            ldsm_x4(ah[mt], abase + off);
        }
        #pragma unroll
        for (int np = 0; np < 2; np++) {
            uint32_t off = sub + SWZ((wc * 32 + np * 16 + bt * 8 + br) * 128 + kb + bc * 16);
            ldsm_x4(bh[np], bbase + off);
        }
        #pragma unroll
        for (int mt = 0; mt < 2; mt++)
            #pragma unroll
            for (int nt = 0; nt < 4; nt++) {
                uint32_t b0 = bh[nt >> 1][(nt & 1) * 2], b1 = bh[nt >> 1][(nt & 1) * 2 + 1];
                mma_fp16(acc[mt][nt], ah[mt], b0, b1);
            }
    }
}

// 3-stage pipeline, one sync per chunk (16 chunks of K=128).
// load(ci+2) overwrites stage (ci-1)%3; issued only after the sync proving
// all warps completed compute(ci-1).
static __device__ __forceinline__ void run_gemm(
    uint32_t sb, int tid,
    const __half* a, size_t arow0, const __half* w, int u0,
    float (&acc)[2][4][4])
{
    load_chunk(sb, 0, 0, tid, a, arow0, w, u0);
    load_chunk(sb, 1, 1, tid, a, arow0, w, u0);
    #pragma unroll 1
    for (int ci = 0; ci < NCH; ci++) {
        if (ci < NCH - 1) CP_WAIT(1); else CP_WAIT(0);
        __syncthreads();
        if (ci + 2 < NCH)
            load_chunk(sb, (ci + 2) % 3, ci + 2, tid, a, arow0, w, u0);
        compute_chunk(sb, ci % 3, tid, acc);
    }
    __syncthreads();   // all compute done before Cs overlays stage smem
}

static __device__ __forceinline__ void store_cs(float* Cs, int tid, float (&acc)[2][4][4])
{
    int lane = tid & 31, wid = tid >> 5;
    int wr = wid >> 2, wc = wid & 3;
    int r0 = wr * 32 + (lane >> 2), c0 = wc * 32 + 2 * (lane & 3);
    #pragma unroll
    for (int mt = 0; mt < 2; mt++)
        #pragma unroll
        for (int nt = 0; nt < 4; nt++) {
            float* p = Cs + (r0 + mt * 16) * CST + c0 + nt * 8;
            p[0] = acc[mt][nt][0];
            p[1] = acc[mt][nt][1];
            p[8 * CST]     = acc[mt][nt][2];
            p[8 * CST + 1] = acc[mt][nt][3];
        }
}

// ---------------------------------------------------------------------------
// Kernel 1: W GEMM.  grid (16 u-tiles, 256 m-tiles), 512 threads
// ---------------------------------------------------------------------------
__global__ __launch_bounds__(NTHR) void wgemm_tc()
{
    extern __shared__ char smem[];
    uint32_t sb = smem_u32(smem);
    int tid = threadIdx.x;
    size_t m0 = (size_t)blockIdx.y * 128;
    int u0 = blockIdx.x * 64;

    float acc[2][4][4];
    #pragma unroll
    for (int a = 0; a < 2; a++)
        #pragma unroll
        for (int b = 0; b < 4; b++)
            #pragma unroll
            for (int c = 0; c < 4; c++) acc[a][b][c] = 0.f;

    run_gemm(sb, tid, g_xbf, m0, g_bwt, u0, acc);

    float* Cs = (float*)smem;
    store_cs(Cs, tid, acc);
    __syncthreads();

    #pragma unroll 4
    for (int l = 0; l < 16; l++) {
        int pid = tid + l * NTHR;
        int row = pid >> 6, ul = pid & 63;
        float re = Cs[row * CST + ul], im = Cs[row * CST + ul + 64];
        int m = (int)m0 + row;
        int bb = m >> 9, t = m & (TLEN - 1);
        g_W[((size_t)(t + OV) * BSZ + bb) * UDIM + u0 + ul] = make_float2(re, im);
    }
}

// ---------------------------------------------------------------------------
// Grid barrier (128 CTAs co-resident)
// ---------------------------------------------------------------------------
static __device__ __forceinline__ void grid_barrier()
{
    __threadfence();
    __syncthreads();
    if (threadIdx.x == 0) {
        unsigned my = *(volatile unsigned*)&g_bar_phase;
        unsigned rank = atomicAdd(&g_bar_cnt, 1u);
        if (rank == NCTA_SCAN - 1) {
            g_bar_cnt = 0;
            __threadfence();
            *(volatile unsigned*)&g_bar_phase = my + 1u;
        } else {
            while (*(volatile unsigned*)&g_bar_phase == my) __nanosleep(32);
        }
        __threadfence();
    }
    __syncthreads();
}

// ---------------------------------------------------------------------------
// Kernel 2: persistent scan. 48 steps; 128 CTAs = 8 m-tiles x 16 u-tiles.
// ---------------------------------------------------------------------------
__global__ __launch_bounds__(NTHR) void scan_tc(float2* __restrict__ out)
{
    extern __shared__ char smem[];
    uint32_t sb = smem_u32(smem);
    int tid = threadIdx.x;
    size_t m0 = (size_t)(blockIdx.x >> 4) * 128;
    int u0 = (blockIdx.x & 15) * 64;

    for (int s = 0; s < NSTEP; s++) {
        float acc[2][4][4];
        #pragma unroll
        for (int a = 0; a < 2; a++)
            #pragma unroll
            for (int b = 0; b < 4; b++)
                #pragma unroll
                for (int c = 0; c < 4; c++) acc[a][b][c] = 0.f;

        if (s != 0)   // s==0: state exactly zero
            run_gemm(sb, tid, g_z[s & 1], m0, g_awt, u0, acc);

        float* Cs = (float*)smem;
        store_cs(Cs, tid, acc);
        __syncthreads();

        __half* nz = g_z[(s + 1) & 1];
        #pragma unroll 4
        for (int l = 0; l < 16; l++) {
            int pid = tid + l * NTHR;
            int row = pid >> 6, ul = pid & 63;
            float re = Cs[row * CST + ul], im = Cs[row * CST + ul + 64];
            int g = (int)m0 + row;
            int c = g >> 6, bb = g & 63;
            int wslot = c * CLEN + s;
            int u = u0 + ul;
            float2 w = g_W[((size_t)wslot * BSZ + bb) * UDIM + u];
            float zr = re + w.x, zi = im + w.y;
            size_t base = (size_t)g * KREAL + u;
            nz[base]        = __float2half_rn(zr);
            nz[base + 1024] = __float2half_rn(zi);
            if (s >= OV) {
                int tout = wslot - OV;
                float r2 = zr * zr + zi * zi;
                float cc = 2.0f - r2;
                out[((size_t)bb * TLEN + tout) * UDIM + u] =
                    make_float2(fmaf(-OMEGA_F, zi, cc * zr), fmaf(OMEGA_F, zr, cc * zi));
            }
        }
        grid_barrier();
    }
}

// ---------------------------------------------------------------------------
// Launch: 4 graph nodes
// ---------------------------------------------------------------------------
extern "C" void kernel_launch(void* const* d_in, const int* in_sizes, int n_in,
                              void* d_out, int out_size)
{
    const float* xr  = (const float*)d_in[0];
    const float* xi  = (const float*)d_in[1];
    const float* Ar  = (const float*)d_in[2];
    const float* Ai  = (const float*)d_in[3];
    const float* Br  = (const float*)d_in[4];
    const float* Bi  = (const float*)d_in[5];
    const float* z0r = (const float*)d_in[6];
    const float* z0i = (const float*)d_in[7];
    float2* out = (float2*)d_out;

    cudaFuncSetAttribute(wgemm_tc, cudaFuncAttributeMaxDynamicSharedMemorySize, SMEM_DYN);
    cudaFuncSetAttribute(scan_tc,  cudaFuncAttributeMaxDynamicSharedMemorySize, SMEM_DYN);

    pack_tc<<<(KREAL * KREAL) / 256, 256>>>(Ar, Ai, Br, Bi, z0r, z0i);
    xhalf<<<(XROWS * KREAL / 4) / 256, 256>>>(xr, xi);
    wgemm_tc<<<dim3(16, 256), NTHR, SMEM_DYN>>>();
    scan_tc<<<NCTA_SCAN, NTHR, SMEM_DYN>>>(out);
}

// round 14
// speedup vs baseline: 1.4538x; 1.4538x over previous
#include <cuda_runtime.h>
#include <cuda_fp16.h>
#include <cstdint>

#define BSZ    64
#define TLEN   512
#define UDIM   1024
#define KREAL  2048
#define XROWS  32768
#define OMEGA_F 0.006135923151542565f
#define OV     16
#define CLEN   32
#define NSTEP  (CLEN + OV)          // 48
#define SROWS  1024
#define NCTA_SCAN 128
#define NTHR   512

// smem: four stages x (A 16K + B 16K) = 128 KB
#define TB      16384
#define STB     32768
#define SM_A(st) ((st)*STB)
#define SM_B(st) ((st)*STB + TB)
#define SMEM_DYN 131072
#define CST     132                  // Cs f32 row stride (epilogue overlay)

// ---------------------------------------------------------------------------
// Device scratch (static; no runtime allocation)
// ---------------------------------------------------------------------------
__device__ float2 g_W[(size_t)(TLEN + OV) * BSZ * UDIM];            // fp32 W; slots 0..OV-1 pad (z0 at OV-1)
__device__ __align__(16) __half g_awt[(size_t)KREAL * KREAL];       // A weights [n][k] fp16, x0.5
__device__ __align__(16) __half g_bwt[(size_t)KREAL * KREAL];       // B weights
__device__ __align__(16) __half g_xbf[(size_t)XROWS * KREAL];       // x fp16 [row][k]
__device__ __align__(16) __half g_z[2][(size_t)SROWS * KREAL];      // state double buffer fp16
__device__ unsigned g_bar_cnt, g_bar_phase;

// ---------------------------------------------------------------------------
// Helpers
// ---------------------------------------------------------------------------
#define SWZ(x) ((x) ^ (((x) >> 3) & 0x70))

static __device__ __forceinline__ uint32_t smem_u32(const void* p) {
    uint32_t a;
    asm("{ .reg .u64 t; cvta.to.shared.u64 t, %1; cvt.u32.u64 %0, t; }" : "=r"(a) : "l"(p));
    return a;
}
#define CP16(saddr, gptr) \
    asm volatile("cp.async.cg.shared.global [%0], [%1], 16;" :: "r"(saddr), "l"(gptr))
#define CP_COMMIT() asm volatile("cp.async.commit_group;" ::: "memory")
#define CP_WAIT(n)  asm volatile("cp.async.wait_group %0;" :: "n"(n) : "memory")

static __device__ __forceinline__ void ldsm_x4(uint32_t (&r)[4], uint32_t a) {
    asm volatile("ldmatrix.sync.aligned.m8n8.x4.shared.b16 {%0,%1,%2,%3}, [%4];"
        : "=r"(r[0]), "=r"(r[1]), "=r"(r[2]), "=r"(r[3]) : "r"(a));
}
static __device__ __forceinline__ void mma_fp16(
    float (&d)[4], const uint32_t (&a)[4], uint32_t b0, uint32_t b1)
{
    asm volatile("mma.sync.aligned.m16n8k16.row.col.f32.f16.f16.f32 "
        "{%0,%1,%2,%3}, {%4,%5,%6,%7}, {%8,%9}, {%0,%1,%2,%3};"
        : "+f"(d[0]), "+f"(d[1]), "+f"(d[2]), "+f"(d[3])
        : "r"(a[0]), "r"(a[1]), "r"(a[2]), "r"(a[3]), "r"(b0), "r"(b1));
}
static __device__ __forceinline__ uint32_t pkh(__half a, __half b) {
    return (uint32_t)__half_as_ushort(a) | ((uint32_t)__half_as_ushort(b) << 16);
}

// ---------------------------------------------------------------------------
// Kernel 0a: pack weights (transposed real embedding, 0.5-scaled, fp16),
//            init W pad (z0 at slot OV-1), zero state buf 0
// ---------------------------------------------------------------------------
__global__ __launch_bounds__(256) void pack_tc(
    const float* __restrict__ Ar, const float* __restrict__ Ai,
    const float* __restrict__ Br, const float* __restrict__ Bi,
    const float* __restrict__ z0r, const float* __restrict__ z0i)
{
    int i = blockIdx.x * 256 + threadIdx.x;   // 0 .. 4M-1
    {
        int n = i >> 11, k = i & 2047;
        int kk = k & 1023, nn = n & 1023;
        float a, b;
        if (k < 1024) {
            if (n < 1024) { a = Ar[k*1024 + n];  b = Br[k*1024 + n];  }
            else          { a = Ai[k*1024 + nn]; b = Bi[k*1024 + nn]; }
        } else {
            if (n < 1024) { a = -Ai[kk*1024 + n];  b = -Bi[kk*1024 + n];  }
            else          { a =  Ar[kk*1024 + nn]; b =  Br[kk*1024 + nn]; }
        }
        g_awt[i] = __float2half_rn(0.5f * a);
        g_bwt[i] = __float2half_rn(0.5f * b);
    }
    if (i < OV * BSZ * UDIM) {                // 1.05M: W pad, z0 at slot OV-1
        int slot = i >> 16, r = i & 65535;
        g_W[i] = (slot == OV - 1) ? make_float2(z0r[r], z0i[r]) : make_float2(0.f, 0.f);
    }
    if (i < (int)(SROWS * KREAL / 2))          // 1.05M u32 = state buf 0
        ((uint32_t*)g_z[0])[i] = 0u;
}

// ---------------------------------------------------------------------------
// Kernel 0b: convert x to fp16, k-layout [re(1024) | im(1024)]
// ---------------------------------------------------------------------------
__global__ __launch_bounds__(256) void xhalf(
    const float* __restrict__ xr, const float* __restrict__ xi)
{
    int i = blockIdx.x * 256 + threadIdx.x;
    int row = i >> 9;
    int kq = (i & 511) * 4;
    const float* src = (kq < 1024) ? xr : xi;
    float4 v = *(const float4*)(src + (size_t)row * 1024 + (kq & 1023));
    *(uint2*)(g_xbf + (size_t)row * KREAL + kq) = make_uint2(
        pkh(__float2half_rn(v.x), __float2half_rn(v.y)),
        pkh(__float2half_rn(v.z), __float2half_rn(v.w)));
}

// ---------------------------------------------------------------------------
// GEMM machinery.  512 threads, warp grid 4x4 (each warp 32 rows x 32 cols).
//   A: activations fp16 [row][2048], rows arow0..+127, K chunks of 64
//   B: weights fp16 [n][2048]; smem row j<64 -> n=u0+j (re), j>=64 -> im half
// ---------------------------------------------------------------------------
static __device__ __forceinline__ void load_chunk(
    uint32_t sb, int st, int ci, int tid,
    const __half* a, size_t arow0, const __half* w, int u0)
{
    #pragma unroll
    for (int l = 0; l < 2; l++) {
        int idx = tid + l * NTHR;
        int row = idx >> 3, g16 = idx & 7;
        CP16(sb + SM_A(st) + SWZ(row * 128 + g16 * 16),
             a + (arow0 + row) * KREAL + ci * 64 + g16 * 8);
    }
    #pragma unroll
    for (int l = 0; l < 2; l++) {
        int idx = tid + l * NTHR;
        int j = idx >> 3, g16 = idx & 7;
        int n = u0 + j + ((j >= 64) ? 960 : 0);
        CP16(sb + SM_B(st) + SWZ(j * 128 + g16 * 16),
             w + (size_t)n * KREAL + ci * 64 + g16 * 8);
    }
    CP_COMMIT();
}

static __device__ __forceinline__ void compute_chunk(
    uint32_t sb, int st, int tid, float (&acc)[2][4][4])
{
    int lane = tid & 31, wid = tid >> 5;
    int wr = wid >> 2, wc = wid & 3;
    uint32_t abase = sb + SM_A(st);
    uint32_t bbase = sb + SM_B(st);
    int ar = lane & 15, ac = lane >> 4;
    int br = lane & 7, bc = (lane >> 3) & 1, bt = lane >> 4;

    #pragma unroll
    for (int k16 = 0; k16 < 4; k16++) {
        int kb = k16 * 32;
        uint32_t ah[2][4], bh[2][4];
        #pragma unroll
        for (int mt = 0; mt < 2; mt++) {
            uint32_t off = SWZ((wr * 32 + mt * 16 + ar) * 128 + kb + ac * 16);
            ldsm_x4(ah[mt], abase + off);
        }
        #pragma unroll
        for (int np = 0; np < 2; np++) {
            uint32_t off = SWZ((wc * 32 + np * 16 + bt * 8 + br) * 128 + kb + bc * 16);
            ldsm_x4(bh[np], bbase + off);
        }
        #pragma unroll
        for (int mt = 0; mt < 2; mt++)
            #pragma unroll
            for (int nt = 0; nt < 4; nt++) {
                uint32_t b0 = bh[nt >> 1][(nt & 1) * 2], b1 = bh[nt >> 1][(nt & 1) * 2 + 1];
                mma_fp16(acc[mt][nt], ah[mt], b0, b1);
            }
    }
}

// 4-stage pipeline, one sync per chunk (32 chunks of K=64).
// load(ci+3) overwrites stage (ci-1)%4; issued only after the sync proving
// all warps completed compute(ci-1).
static __device__ __forceinline__ void run_gemm(
    uint32_t sb, int tid,
    const __half* a, size_t arow0, const __half* w, int u0,
    float (&acc)[2][4][4])
{
    load_chunk(sb, 0, 0, tid, a, arow0, w, u0);
    load_chunk(sb, 1, 1, tid, a, arow0, w, u0);
    load_chunk(sb, 2, 2, tid, a, arow0, w, u0);
    #pragma unroll 1
    for (int ci = 0; ci < 32; ci++) {
        if (ci < 30)       CP_WAIT(2);
        else if (ci == 30) CP_WAIT(1);
        else               CP_WAIT(0);
        __syncthreads();
        if (ci + 3 < 32)
            load_chunk(sb, (ci + 3) & 3, ci + 3, tid, a, arow0, w, u0);
        compute_chunk(sb, ci & 3, tid, acc);
    }
    __syncthreads();   // all compute done before Cs overlays stage smem
}

static __device__ __forceinline__ void store_cs(float* Cs, int tid, float (&acc)[2][4][4])
{
    int lane = tid & 31, wid = tid >> 5;
    int wr = wid >> 2, wc = wid & 3;
    int r0 = wr * 32 + (lane >> 2), c0 = wc * 32 + 2 * (lane & 3);
    #pragma unroll
    for (int mt = 0; mt < 2; mt++)
        #pragma unroll
        for (int nt = 0; nt < 4; nt++) {
            float* p = Cs + (r0 + mt * 16) * CST + c0 + nt * 8;
            p[0] = acc[mt][nt][0];
            p[1] = acc[mt][nt][1];
            p[8 * CST]     = acc[mt][nt][2];
            p[8 * CST + 1] = acc[mt][nt][3];
        }
}

// ---------------------------------------------------------------------------
// Kernel 1: W GEMM.  grid (16 u-tiles, 256 m-tiles), 512 threads
// ---------------------------------------------------------------------------
__global__ __launch_bounds__(NTHR) void wgemm_tc()
{
    extern __shared__ char smem[];
    uint32_t sb = smem_u32(smem);
    int tid = threadIdx.x;
    size_t m0 = (size_t)blockIdx.y * 128;
    int u0 = blockIdx.x * 64;

    float acc[2][4][4];
    #pragma unroll
    for (int a = 0; a < 2; a++)
        #pragma unroll
        for (int b = 0; b < 4; b++)
            #pragma unroll
            for (int c = 0; c < 4; c++) acc[a][b][c] = 0.f;

    run_gemm(sb, tid, g_xbf, m0, g_bwt, u0, acc);

    float* Cs = (float*)smem;
    store_cs(Cs, tid, acc);
    __syncthreads();

    #pragma unroll 4
    for (int l = 0; l < 16; l++) {
        int pid = tid + l * NTHR;
        int row = pid >> 6, ul = pid & 63;
        float re = Cs[row * CST + ul], im = Cs[row * CST + ul + 64];
        int m = (int)m0 + row;
        int bb = m >> 9, t = m & (TLEN - 1);
        g_W[((size_t)(t + OV) * BSZ + bb) * UDIM + u0 + ul] = make_float2(re, im);
    }
}

// ---------------------------------------------------------------------------
// Grid barrier (128 CTAs co-resident)
// ---------------------------------------------------------------------------
static __device__ __forceinline__ void grid_barrier()
{
    __threadfence();
    __syncthreads();
    if (threadIdx.x == 0) {
        unsigned my = *(volatile unsigned*)&g_bar_phase;
        unsigned rank = atomicAdd(&g_bar_cnt, 1u);
        if (rank == NCTA_SCAN - 1) {
            g_bar_cnt = 0;
            __threadfence();
            *(volatile unsigned*)&g_bar_phase = my + 1u;
        } else {
            while (*(volatile unsigned*)&g_bar_phase == my) __nanosleep(32);
        }
        __threadfence();
    }
    __syncthreads();
}

// ---------------------------------------------------------------------------
// Kernel 2: persistent scan. 48 steps; 128 CTAs = 8 m-tiles x 16 u-tiles.
// ---------------------------------------------------------------------------
__global__ __launch_bounds__(NTHR) void scan_tc(float2* __restrict__ out)
{
    extern __shared__ char smem[];
    uint32_t sb = smem_u32(smem);
    int tid = threadIdx.x;
    size_t m0 = (size_t)(blockIdx.x >> 4) * 128;
    int u0 = (blockIdx.x & 15) * 64;

    for (int s = 0; s < NSTEP; s++) {
        float acc[2][4][4];
        #pragma unroll
        for (int a = 0; a < 2; a++)
            #pragma unroll
            for (int b = 0; b < 4; b++)
                #pragma unroll
                for (int c = 0; c < 4; c++) acc[a][b][c] = 0.f;

        if (s != 0)   // s==0: state exactly zero
            run_gemm(sb, tid, g_z[s & 1], m0, g_awt, u0, acc);

        float* Cs = (float*)smem;
        store_cs(Cs, tid, acc);
        __syncthreads();

        __half* nz = g_z[(s + 1) & 1];
        #pragma unroll 4
        for (int l = 0; l < 16; l++) {
            int pid = tid + l * NTHR;
            int row = pid >> 6, ul = pid & 63;
            float re = Cs[row * CST + ul], im = Cs[row * CST + ul + 64];
            int g = (int)m0 + row;
            int c = g >> 6, bb = g & 63;
            int wslot = c * CLEN + s;
            int u = u0 + ul;
            float2 w = g_W[((size_t)wslot * BSZ + bb) * UDIM + u];
            float zr = re + w.x, zi = im + w.y;
            size_t base = (size_t)g * KREAL + u;
            nz[base]        = __float2half_rn(zr);
            nz[base + 1024] = __float2half_rn(zi);
            if (s >= OV) {
                int tout = wslot - OV;
                float r2 = zr * zr + zi * zi;
                float cc = 2.0f - r2;
                out[((size_t)bb * TLEN + tout) * UDIM + u] =
                    make_float2(fmaf(-OMEGA_F, zi, cc * zr), fmaf(OMEGA_F, zr, cc * zi));
            }
        }
        grid_barrier();
    }
}

// ---------------------------------------------------------------------------
// Launch: 4 graph nodes
// ---------------------------------------------------------------------------
extern "C" void kernel_launch(void* const* d_in, const int* in_sizes, int n_in,
                              void* d_out, int out_size)
{
    const float* xr  = (const float*)d_in[0];
    const float* xi  = (const float*)d_in[1];
    const float* Ar  = (const float*)d_in[2];
    const float* Ai  = (const float*)d_in[3];
    const float* Br  = (const float*)d_in[4];
    const float* Bi  = (const float*)d_in[5];
    const float* z0r = (const float*)d_in[6];
    const float* z0i = (const float*)d_in[7];
    float2* out = (float2*)d_out;

    cudaFuncSetAttribute(wgemm_tc, cudaFuncAttributeMaxDynamicSharedMemorySize, SMEM_DYN);
    cudaFuncSetAttribute(scan_tc,  cudaFuncAttributeMaxDynamicSharedMemorySize, SMEM_DYN);

    pack_tc<<<(KREAL * KREAL) / 256, 256>>>(Ar, Ai, Br, Bi, z0r, z0i);
    xhalf<<<(XROWS * KREAL / 4) / 256, 256>>>(xr, xi);
    wgemm_tc<<<dim3(16, 256), NTHR, SMEM_DYN>>>();
    scan_tc<<<NCTA_SCAN, NTHR, SMEM_DYN>>>(out);
}

// round 15
// speedup vs baseline: 1.6081x; 1.1061x over previous
#include <cuda_runtime.h>
#include <cuda_fp16.h>
#include <cstdint>

#define BSZ    64
#define TLEN   512
#define UDIM   1024
#define KREAL  2048
#define XROWS  32768
#define OMEGA_F 0.006135923151542565f
#define OV     12
#define CLEN   32
#define NSTEP  (CLEN + OV)          // 44
#define SROWS  1024
#define NCTA_SCAN 128
#define NTHR   512

// smem: four stages x (A 16K + B 16K) = 128 KB
#define TB      16384
#define STB     32768
#define SM_A(st) ((st)*STB)
#define SM_B(st) ((st)*STB + TB)
#define SMEM_DYN 131072

// ---------------------------------------------------------------------------
// Device scratch (static; no runtime allocation)
// ---------------------------------------------------------------------------
__device__ float2 g_W[(size_t)(TLEN + OV) * BSZ * UDIM];            // fp32 W; slots 0..OV-1 pad (z0 at OV-1)
__device__ __align__(16) __half g_awt[(size_t)KREAL * KREAL];       // A weights [n][k] fp16, x0.5
__device__ __align__(16) __half g_bwt[(size_t)KREAL * KREAL];       // B weights
__device__ __align__(16) __half g_xbf[(size_t)XROWS * KREAL];       // x fp16 [row][k]
__device__ __align__(16) __half g_z[2][(size_t)SROWS * KREAL];      // state double buffer fp16
__device__ unsigned g_bar_cnt, g_bar_phase;

// ---------------------------------------------------------------------------
// Helpers
// ---------------------------------------------------------------------------
#define SWZ(x) ((x) ^ (((x) >> 3) & 0x70))

static __device__ __forceinline__ uint32_t smem_u32(const void* p) {
    uint32_t a;
    asm("{ .reg .u64 t; cvta.to.shared.u64 t, %1; cvt.u32.u64 %0, t; }" : "=r"(a) : "l"(p));
    return a;
}
#define CP16(saddr, gptr) \
    asm volatile("cp.async.cg.shared.global [%0], [%1], 16;" :: "r"(saddr), "l"(gptr))
#define CP_COMMIT() asm volatile("cp.async.commit_group;" ::: "memory")
#define CP_WAIT(n)  asm volatile("cp.async.wait_group %0;" :: "n"(n) : "memory")

static __device__ __forceinline__ void ldsm_x4(uint32_t (&r)[4], uint32_t a) {
    asm volatile("ldmatrix.sync.aligned.m8n8.x4.shared.b16 {%0,%1,%2,%3}, [%4];"
        : "=r"(r[0]), "=r"(r[1]), "=r"(r[2]), "=r"(r[3]) : "r"(a));
}
static __device__ __forceinline__ void mma_fp16(
    float (&d)[4], const uint32_t (&a)[4], uint32_t b0, uint32_t b1)
{
    asm volatile("mma.sync.aligned.m16n8k16.row.col.f32.f16.f16.f32 "
        "{%0,%1,%2,%3}, {%4,%5,%6,%7}, {%8,%9}, {%0,%1,%2,%3};"
        : "+f"(d[0]), "+f"(d[1]), "+f"(d[2]), "+f"(d[3])
        : "r"(a[0]), "r"(a[1]), "r"(a[2]), "r"(a[3]), "r"(b0), "r"(b1));
}
static __device__ __forceinline__ uint32_t pkh(__half a, __half b) {
    return (uint32_t)__half_as_ushort(a) | ((uint32_t)__half_as_ushort(b) << 16);
}

// ---------------------------------------------------------------------------
// Kernel 0a: pack weights (transposed real embedding, 0.5-scaled, fp16),
//            init W pad (z0 at slot OV-1), zero state buf 0
// ---------------------------------------------------------------------------
__global__ __launch_bounds__(256) void pack_tc(
    const float* __restrict__ Ar, const float* __restrict__ Ai,
    const float* __restrict__ Br, const float* __restrict__ Bi,
    const float* __restrict__ z0r, const float* __restrict__ z0i)
{
    int i = blockIdx.x * 256 + threadIdx.x;   // 0 .. 4M-1
    {
        int n = i >> 11, k = i & 2047;
        int kk = k & 1023, nn = n & 1023;
        float a, b;
        if (k < 1024) {
            if (n < 1024) { a = Ar[k*1024 + n];  b = Br[k*1024 + n];  }
            else          { a = Ai[k*1024 + nn]; b = Bi[k*1024 + nn]; }
        } else {
            if (n < 1024) { a = -Ai[kk*1024 + n];  b = -Bi[kk*1024 + n];  }
            else          { a =  Ar[kk*1024 + nn]; b =  Br[kk*1024 + nn]; }
        }
        g_awt[i] = __float2half_rn(0.5f * a);
        g_bwt[i] = __float2half_rn(0.5f * b);
    }
    if (i < OV * BSZ * UDIM) {                // W pad, z0 at slot OV-1
        int slot = i >> 16, r = i & 65535;
        g_W[i] = (slot == OV - 1) ? make_float2(z0r[r], z0i[r]) : make_float2(0.f, 0.f);
    }
    if (i < (int)(SROWS * KREAL / 2))          // 1.05M u32 = state buf 0
        ((uint32_t*)g_z[0])[i] = 0u;
}

// ---------------------------------------------------------------------------
// Kernel 0b: convert x to fp16, k-layout [re(1024) | im(1024)]
// ---------------------------------------------------------------------------
__global__ __launch_bounds__(256) void xhalf(
    const float* __restrict__ xr, const float* __restrict__ xi)
{
    int i = blockIdx.x * 256 + threadIdx.x;
    int row = i >> 9;
    int kq = (i & 511) * 4;
    const float* src = (kq < 1024) ? xr : xi;
    float4 v = *(const float4*)(src + (size_t)row * 1024 + (kq & 1023));
    *(uint2*)(g_xbf + (size_t)row * KREAL + kq) = make_uint2(
        pkh(__float2half_rn(v.x), __float2half_rn(v.y)),
        pkh(__float2half_rn(v.z), __float2half_rn(v.w)));
}

// ---------------------------------------------------------------------------
// GEMM machinery.  512 threads, warp grid 4x4 (each warp 32 rows x 32 cols).
//   A: activations fp16 [row][2048], rows arow0..+127, K chunks of 64
//   B: weights fp16 [n][2048]; INTERLEAVED smem rows:
//       j even -> n = u0 + j/2       (re weight row)
//       j odd  -> n = 1024 + u0 + j/2 (im weight row)
//   => mma output cols (2u', 2u'+1) = (re, im) of u = u0 + u' in ONE thread.
// ---------------------------------------------------------------------------
static __device__ __forceinline__ void load_chunk(
    uint32_t sb, int st, int ci, int tid,
    const __half* a, size_t arow0, const __half* w, int u0)
{
    #pragma unroll
    for (int l = 0; l < 2; l++) {
        int idx = tid + l * NTHR;
        int row = idx >> 3, g16 = idx & 7;
        CP16(sb + SM_A(st) + SWZ(row * 128 + g16 * 16),
             a + (arow0 + row) * KREAL + ci * 64 + g16 * 8);
    }
    #pragma unroll
    for (int l = 0; l < 2; l++) {
        int idx = tid + l * NTHR;
        int j = idx >> 3, g16 = idx & 7;
        int n = u0 + (j >> 1) + ((j & 1) ? 1024 : 0);
        CP16(sb + SM_B(st) + SWZ(j * 128 + g16 * 16),
             w + (size_t)n * KREAL + ci * 64 + g16 * 8);
    }
    CP_COMMIT();
}

static __device__ __forceinline__ void compute_chunk(
    uint32_t sb, int st, int tid, float (&acc)[2][4][4])
{
    int lane = tid & 31, wid = tid >> 5;
    int wr = wid >> 2, wc = wid & 3;
    uint32_t abase = sb + SM_A(st);
    uint32_t bbase = sb + SM_B(st);
    int ar = lane & 15, ac = lane >> 4;
    int br = lane & 7, bc = (lane >> 3) & 1, bt = lane >> 4;

    #pragma unroll
    for (int k16 = 0; k16 < 4; k16++) {
        int kb = k16 * 32;
        uint32_t ah[2][4], bh[2][4];
        #pragma unroll
        for (int mt = 0; mt < 2; mt++) {
            uint32_t off = SWZ((wr * 32 + mt * 16 + ar) * 128 + kb + ac * 16);
            ldsm_x4(ah[mt], abase + off);
        }
        #pragma unroll
        for (int np = 0; np < 2; np++) {
            uint32_t off = SWZ((wc * 32 + np * 16 + bt * 8 + br) * 128 + kb + bc * 16);
            ldsm_x4(bh[np], bbase + off);
        }
        #pragma unroll
        for (int mt = 0; mt < 2; mt++)
            #pragma unroll
            for (int nt = 0; nt < 4; nt++) {
                uint32_t b0 = bh[nt >> 1][(nt & 1) * 2], b1 = bh[nt >> 1][(nt & 1) * 2 + 1];
                mma_fp16(acc[mt][nt], ah[mt], b0, b1);
            }
    }
}

// 4-stage pipeline, one sync per chunk (32 chunks of K=64).
// load(ci+3) overwrites stage (ci-1)%4; issued only after the sync proving
// all warps completed compute(ci-1).  NOTE: no trailing sync — epilogues are
// register-only; smem stage reuse across scan steps is fenced by the grid
// barrier (which contains __syncthreads).
static __device__ __forceinline__ void run_gemm(
    uint32_t sb, int tid,
    const __half* a, size_t arow0, const __half* w, int u0,
    float (&acc)[2][4][4])
{
    load_chunk(sb, 0, 0, tid, a, arow0, w, u0);
    load_chunk(sb, 1, 1, tid, a, arow0, w, u0);
    load_chunk(sb, 2, 2, tid, a, arow0, w, u0);
    #pragma unroll 1
    for (int ci = 0; ci < 32; ci++) {
        if (ci < 30)       CP_WAIT(2);
        else if (ci == 30) CP_WAIT(1);
        else               CP_WAIT(0);
        __syncthreads();
        if (ci + 3 < 32)
            load_chunk(sb, (ci + 3) & 3, ci + 3, tid, a, arow0, w, u0);
        compute_chunk(sb, ci & 3, tid, acc);
    }
}

// ---------------------------------------------------------------------------
// Kernel 1: W GEMM.  grid (16 u-tiles, 256 m-tiles), 512 threads.
// Register-direct epilogue: each thread owns (re,im) pairs.
// ---------------------------------------------------------------------------
__global__ __launch_bounds__(NTHR) void wgemm_tc()
{
    extern __shared__ char smem[];
    uint32_t sb = smem_u32(smem);
    int tid = threadIdx.x;
    size_t m0 = (size_t)blockIdx.y * 128;
    int u0 = blockIdx.x * 64;

    float acc[2][4][4];
    #pragma unroll
    for (int a = 0; a < 2; a++)
        #pragma unroll
        for (int b = 0; b < 4; b++)
            #pragma unroll
            for (int c = 0; c < 4; c++) acc[a][b][c] = 0.f;

    run_gemm(sb, tid, g_xbf, m0, g_bwt, u0, acc);

    int lane = tid & 31, wid = tid >> 5;
    int wr = wid >> 2, wc = wid & 3;
    int r0 = wr * 32 + (lane >> 2);
    int ub = u0 + wc * 16 + (lane & 3);
    #pragma unroll
    for (int mt = 0; mt < 2; mt++)
        #pragma unroll
        for (int h = 0; h < 2; h++) {
            int m = (int)m0 + r0 + mt * 16 + h * 8;
            int bb = m >> 9, t = m & (TLEN - 1);
            size_t base = ((size_t)(t + OV) * BSZ + bb) * UDIM;
            #pragma unroll
            for (int nt = 0; nt < 4; nt++)
                g_W[base + ub + nt * 4] =
                    make_float2(acc[mt][nt][2 * h], acc[mt][nt][2 * h + 1]);
        }
}

// ---------------------------------------------------------------------------
// Grid barrier (128 CTAs co-resident)
// ---------------------------------------------------------------------------
static __device__ __forceinline__ void grid_barrier()
{
    __threadfence();
    __syncthreads();
    if (threadIdx.x == 0) {
        unsigned my = *(volatile unsigned*)&g_bar_phase;
        unsigned rank = atomicAdd(&g_bar_cnt, 1u);
        if (rank == NCTA_SCAN - 1) {
            g_bar_cnt = 0;
            __threadfence();
            *(volatile unsigned*)&g_bar_phase = my + 1u;
        } else {
            while (*(volatile unsigned*)&g_bar_phase == my) __nanosleep(32);
        }
        __threadfence();
    }
    __syncthreads();
}

// ---------------------------------------------------------------------------
// Kernel 2: persistent scan. 44 steps; 128 CTAs = 8 m-tiles x 16 u-tiles.
// Register-direct epilogue (no smem roundtrip, no extra syncs).
// ---------------------------------------------------------------------------
__global__ __launch_bounds__(NTHR) void scan_tc(float2* __restrict__ out)
{
    extern __shared__ char smem[];
    uint32_t sb = smem_u32(smem);
    int tid = threadIdx.x;
    size_t m0 = (size_t)(blockIdx.x >> 4) * 128;
    int u0 = (blockIdx.x & 15) * 64;

    int lane = tid & 31, wid = tid >> 5;
    int wr = wid >> 2, wc = wid & 3;
    int r0 = wr * 32 + (lane >> 2);
    int ub = u0 + wc * 16 + (lane & 3);

    for (int s = 0; s < NSTEP; s++) {
        float acc[2][4][4];
        #pragma unroll
        for (int a = 0; a < 2; a++)
            #pragma unroll
            for (int b = 0; b < 4; b++)
                #pragma unroll
                for (int c = 0; c < 4; c++) acc[a][b][c] = 0.f;

        if (s != 0)   // s==0: state exactly zero
            run_gemm(sb, tid, g_z[s & 1], m0, g_awt, u0, acc);

        __half* nz = g_z[(s + 1) & 1];
        #pragma unroll
        for (int mt = 0; mt < 2; mt++)
            #pragma unroll
            for (int h = 0; h < 2; h++) {
                int g = (int)m0 + r0 + mt * 16 + h * 8;
                int c = g >> 6, bb = g & 63;
                int wslot = c * CLEN + s;
                size_t wbase = ((size_t)wslot * BSZ + bb) * UDIM;
                size_t zbase = (size_t)g * KREAL;
                #pragma unroll
                for (int nt = 0; nt < 4; nt++) {
                    int u = ub + nt * 4;
                    float2 w = g_W[wbase + u];
                    float zr = acc[mt][nt][2 * h]     + w.x;
                    float zi = acc[mt][nt][2 * h + 1] + w.y;
                    nz[zbase + u]        = __float2half_rn(zr);
                    nz[zbase + u + 1024] = __float2half_rn(zi);
                    if (s >= OV) {
                        int tout = wslot - OV;
                        float r2 = zr * zr + zi * zi;
                        float cc = 2.0f - r2;
                        out[((size_t)bb * TLEN + tout) * UDIM + u] =
                            make_float2(fmaf(-OMEGA_F, zi, cc * zr),
                                        fmaf( OMEGA_F, zr, cc * zi));
                    }
                }
            }
        grid_barrier();
    }
}

// ---------------------------------------------------------------------------
// Launch: 4 graph nodes
// ---------------------------------------------------------------------------
extern "C" void kernel_launch(void* const* d_in, const int* in_sizes, int n_in,
                              void* d_out, int out_size)
{
    const float* xr  = (const float*)d_in[0];
    const float* xi  = (const float*)d_in[1];
    const float* Ar  = (const float*)d_in[2];
    const float* Ai  = (const float*)d_in[3];
    const float* Br  = (const float*)d_in[4];
    const float* Bi  = (const float*)d_in[5];
    const float* z0r = (const float*)d_in[6];
    const float* z0i = (const float*)d_in[7];
    float2* out = (float2*)d_out;

    cudaFuncSetAttribute(wgemm_tc, cudaFuncAttributeMaxDynamicSharedMemorySize, SMEM_DYN);
    cudaFuncSetAttribute(scan_tc,  cudaFuncAttributeMaxDynamicSharedMemorySize, SMEM_DYN);

    pack_tc<<<(KREAL * KREAL) / 256, 256>>>(Ar, Ai, Br, Bi, z0r, z0i);
    xhalf<<<(XROWS * KREAL / 4) / 256, 256>>>(xr, xi);
    wgemm_tc<<<dim3(16, 256), NTHR, SMEM_DYN>>>();
    scan_tc<<<NCTA_SCAN, NTHR, SMEM_DYN>>>(out);
}

// round 16
// speedup vs baseline: 1.7021x; 1.0584x over previous
#include <cuda_runtime.h>
#include <cuda_fp16.h>
#include <cstdint>

#define BSZ    64
#define TLEN   512
#define UDIM   1024
#define KREAL  2048
#define XROWS  32768
#define OMEGA_F 0.006135923151542565f
#define OV     12
#define CLEN   32
#define NSTEP  (CLEN + OV)          // 44
#define SROWS  1024
#define NCTA_SCAN 128
#define NTHR   512

// smem: four stages x (A 16K + B 16K) = 128 KB, then W buffer (128 x 528B)
#define TB      16384
#define STB     32768
#define SM_A(st) ((st)*STB)
#define SM_B(st) ((st)*STB + TB)
#define WOFF    131072
#define WPITCH  528                  // 16B-aligned, bank-staggered row pitch
#define SMEM_SCAN (WOFF + 128 * WPITCH)   // 198656
#define SMEM_WG 131072

// ---------------------------------------------------------------------------
// Device scratch (static; no runtime allocation)
// ---------------------------------------------------------------------------
__device__ float2 g_W[(size_t)(TLEN + OV) * BSZ * UDIM];            // fp32 W; slots 0..OV-1 pad (z0 at OV-1)
__device__ __align__(16) __half g_awt[(size_t)KREAL * KREAL];       // A weights [n][k] fp16, x0.5
__device__ __align__(16) __half g_bwt[(size_t)KREAL * KREAL];       // B weights
__device__ __align__(16) __half g_xbf[(size_t)XROWS * KREAL];       // x fp16 [row][k]
__device__ __align__(16) __half g_z[2][(size_t)SROWS * KREAL];      // state double buffer fp16
__device__ unsigned g_bar_cnt, g_bar_phase;

// ---------------------------------------------------------------------------
// Helpers
// ---------------------------------------------------------------------------
#define SWZ(x) ((x) ^ (((x) >> 3) & 0x70))

static __device__ __forceinline__ uint32_t smem_u32(const void* p) {
    uint32_t a;
    asm("{ .reg .u64 t; cvta.to.shared.u64 t, %1; cvt.u32.u64 %0, t; }" : "=r"(a) : "l"(p));
    return a;
}
#define CP16(saddr, gptr) \
    asm volatile("cp.async.cg.shared.global [%0], [%1], 16;" :: "r"(saddr), "l"(gptr))
#define CP_COMMIT() asm volatile("cp.async.commit_group;" ::: "memory")
#define CP_WAIT(n)  asm volatile("cp.async.wait_group %0;" :: "n"(n) : "memory")

static __device__ __forceinline__ void ldsm_x4(uint32_t (&r)[4], uint32_t a) {
    asm volatile("ldmatrix.sync.aligned.m8n8.x4.shared.b16 {%0,%1,%2,%3}, [%4];"
        : "=r"(r[0]), "=r"(r[1]), "=r"(r[2]), "=r"(r[3]) : "r"(a));
}
static __device__ __forceinline__ void mma_fp16(
    float (&d)[4], const uint32_t (&a)[4], uint32_t b0, uint32_t b1)
{
    asm volatile("mma.sync.aligned.m16n8k16.row.col.f32.f16.f16.f32 "
        "{%0,%1,%2,%3}, {%4,%5,%6,%7}, {%8,%9}, {%0,%1,%2,%3};"
        : "+f"(d[0]), "+f"(d[1]), "+f"(d[2]), "+f"(d[3])
        : "r"(a[0]), "r"(a[1]), "r"(a[2]), "r"(a[3]), "r"(b0), "r"(b1));
}
static __device__ __forceinline__ uint32_t pkh(__half a, __half b) {
    return (uint32_t)__half_as_ushort(a) | ((uint32_t)__half_as_ushort(b) << 16);
}

// ---------------------------------------------------------------------------
// Kernel 0a: pack weights (transposed real embedding, 0.5-scaled, fp16),
//            init W pad (z0 at slot OV-1), zero state buf 0
// ---------------------------------------------------------------------------
__global__ __launch_bounds__(256) void pack_tc(
    const float* __restrict__ Ar, const float* __restrict__ Ai,
    const float* __restrict__ Br, const float* __restrict__ Bi,
    const float* __restrict__ z0r, const float* __restrict__ z0i)
{
    int i = blockIdx.x * 256 + threadIdx.x;   // 0 .. 4M-1
    {
        int n = i >> 11, k = i & 2047;
        int kk = k & 1023, nn = n & 1023;
        float a, b;
        if (k < 1024) {
            if (n < 1024) { a = Ar[k*1024 + n];  b = Br[k*1024 + n];  }
            else          { a = Ai[k*1024 + nn]; b = Bi[k*1024 + nn]; }
        } else {
            if (n < 1024) { a = -Ai[kk*1024 + n];  b = -Bi[kk*1024 + n];  }
            else          { a =  Ar[kk*1024 + nn]; b =  Br[kk*1024 + nn]; }
        }
        g_awt[i] = __float2half_rn(0.5f * a);
        g_bwt[i] = __float2half_rn(0.5f * b);
    }
    if (i < OV * BSZ * UDIM) {                // W pad, z0 at slot OV-1
        int slot = i >> 16, r = i & 65535;
        g_W[i] = (slot == OV - 1) ? make_float2(z0r[r], z0i[r]) : make_float2(0.f, 0.f);
    }
    if (i < (int)(SROWS * KREAL / 2))          // 1.05M u32 = state buf 0
        ((uint32_t*)g_z[0])[i] = 0u;
}

// ---------------------------------------------------------------------------
// Kernel 0b: convert x to fp16, k-layout [re(1024) | im(1024)]
// ---------------------------------------------------------------------------
__global__ __launch_bounds__(256) void xhalf(
    const float* __restrict__ xr, const float* __restrict__ xi)
{
    int i = blockIdx.x * 256 + threadIdx.x;
    int row = i >> 9;
    int kq = (i & 511) * 4;
    const float* src = (kq < 1024) ? xr : xi;
    float4 v = *(const float4*)(src + (size_t)row * 1024 + (kq & 1023));
    *(uint2*)(g_xbf + (size_t)row * KREAL + kq) = make_uint2(
        pkh(__float2half_rn(v.x), __float2half_rn(v.y)),
        pkh(__float2half_rn(v.z), __float2half_rn(v.w)));
}

// ---------------------------------------------------------------------------
// GEMM machinery.  512 threads, warp grid 4x4 (each warp 32 rows x 32 cols).
//   A: activations fp16 [row][2048], rows arow0..+127, K chunks of 64
//   B: weights fp16 [n][2048]; INTERLEAVED smem rows:
//       j even -> n = u0 + j/2       (re weight row)
//       j odd  -> n = 1024 + u0 + j/2 (im weight row)
//   => mma output cols (2u', 2u'+1) = (re, im) of u = u0 + u' in ONE thread.
// ---------------------------------------------------------------------------
static __device__ __forceinline__ void load_half_A(
    uint32_t sb, int st, int ci, int tid, const __half* a, size_t arow0)
{
    #pragma unroll
    for (int l = 0; l < 2; l++) {
        int idx = tid + l * NTHR;
        int row = idx >> 3, g16 = idx & 7;
        CP16(sb + SM_A(st) + SWZ(row * 128 + g16 * 16),
             a + (arow0 + row) * KREAL + ci * 64 + g16 * 8);
    }
    CP_COMMIT();
}
static __device__ __forceinline__ void load_half_B(
    uint32_t sb, int st, int ci, int tid, const __half* w, int u0)
{
    #pragma unroll
    for (int l = 0; l < 2; l++) {
        int idx = tid + l * NTHR;
        int j = idx >> 3, g16 = idx & 7;
        int n = u0 + (j >> 1) + ((j & 1) ? 1024 : 0);
        CP16(sb + SM_B(st) + SWZ(j * 128 + g16 * 16),
             w + (size_t)n * KREAL + ci * 64 + g16 * 8);
    }
    CP_COMMIT();
}
static __device__ __forceinline__ void load_full(
    uint32_t sb, int st, int ci, int tid,
    const __half* a, size_t arow0, const __half* w, int u0)
{
    #pragma unroll
    for (int l = 0; l < 2; l++) {
        int idx = tid + l * NTHR;
        int row = idx >> 3, g16 = idx & 7;
        CP16(sb + SM_A(st) + SWZ(row * 128 + g16 * 16),
             a + (arow0 + row) * KREAL + ci * 64 + g16 * 8);
    }
    #pragma unroll
    for (int l = 0; l < 2; l++) {
        int idx = tid + l * NTHR;
        int j = idx >> 3, g16 = idx & 7;
        int n = u0 + (j >> 1) + ((j & 1) ? 1024 : 0);
        CP16(sb + SM_B(st) + SWZ(j * 128 + g16 * 16),
             w + (size_t)n * KREAL + ci * 64 + g16 * 8);
    }
    CP_COMMIT();
}
// Cooperative W(s) prefetch into padded smem (one group; 4096 x 16B).
static __device__ __forceinline__ void load_W(
    uint32_t sb, int s, int tid, size_t m0, int u0)
{
    #pragma unroll
    for (int l = 0; l < 8; l++) {
        int idx = tid + l * NTHR;            // 0..4095
        int row = idx >> 5, c16 = idx & 31;
        int g = (int)m0 + row;
        int c = g >> 6, bb = g & 63;
        int wslot = c * CLEN + s;
        const float2* src = g_W + (size_t)(wslot * BSZ + bb) * UDIM + u0 + c16 * 2;
        CP16(sb + WOFF + row * WPITCH + c16 * 16, src);
    }
    CP_COMMIT();
}

static __device__ __forceinline__ void compute_chunk(
    uint32_t sb, int st, int tid, float (&acc)[2][4][4])
{
    int lane = tid & 31, wid = tid >> 5;
    int wr = wid >> 2, wc = wid & 3;
    uint32_t abase = sb + SM_A(st);
    uint32_t bbase = sb + SM_B(st);
    int ar = lane & 15, ac = lane >> 4;
    int br = lane & 7, bc = (lane >> 3) & 1, bt = lane >> 4;

    #pragma unroll
    for (int k16 = 0; k16 < 4; k16++) {
        int kb = k16 * 32;
        uint32_t ah[2][4], bh[2][4];
        #pragma unroll
        for (int mt = 0; mt < 2; mt++) {
            uint32_t off = SWZ((wr * 32 + mt * 16 + ar) * 128 + kb + ac * 16);
            ldsm_x4(ah[mt], abase + off);
        }
        #pragma unroll
        for (int np = 0; np < 2; np++) {
            uint32_t off = SWZ((wc * 32 + np * 16 + bt * 8 + br) * 128 + kb + bc * 16);
            ldsm_x4(bh[np], bbase + off);
        }
        #pragma unroll
        for (int mt = 0; mt < 2; mt++)
            #pragma unroll
            for (int nt = 0; nt < 4; nt++) {
                uint32_t b0 = bh[nt >> 1][(nt & 1) * 2], b1 = bh[nt >> 1][(nt & 1) * 2 + 1];
                mma_fp16(acc[mt][nt], ah[mt], b0, b1);
            }
    }
}

// Mainloop for one step.  Entry queue (in order): [B0,B1,B2,W(s)] from the
// pre-barrier prefetch, then [A0,A1,A2] issued here.  wait(2) at ci=0
// completes B0..A0; A1 by ci=1; A2 by ci=2; steady state thereafter.
static __device__ __forceinline__ void run_gemm(
    uint32_t sb, int tid,
    const __half* a, size_t arow0, const __half* w, int u0,
    float (&acc)[2][4][4])
{
    load_half_A(sb, 0, 0, tid, a, arow0);
    load_half_A(sb, 1, 1, tid, a, arow0);
    load_half_A(sb, 2, 2, tid, a, arow0);
    #pragma unroll 1
    for (int ci = 0; ci < 32; ci++) {
        if (ci < 30)       CP_WAIT(2);
        else if (ci == 30) CP_WAIT(1);
        else               CP_WAIT(0);
        __syncthreads();
        if (ci + 3 < 32)
            load_full(sb, (ci + 3) & 3, ci + 3, tid, a, arow0, w, u0);
        compute_chunk(sb, ci & 3, tid, acc);
    }
}

// ---------------------------------------------------------------------------
// Kernel 1: W GEMM.  grid (16 u-tiles, 256 m-tiles), 512 threads.
// Register-direct epilogue; classic 3-stage prologue (no pre-barrier here).
// ---------------------------------------------------------------------------
__global__ __launch_bounds__(NTHR) void wgemm_tc()
{
    extern __shared__ char smem[];
    uint32_t sb = smem_u32(smem);
    int tid = threadIdx.x;
    size_t m0 = (size_t)blockIdx.y * 128;
    int u0 = blockIdx.x * 64;

    float acc[2][4][4];
    #pragma unroll
    for (int a = 0; a < 2; a++)
        #pragma unroll
        for (int b = 0; b < 4; b++)
            #pragma unroll
            for (int c = 0; c < 4; c++) acc[a][b][c] = 0.f;

    load_full(sb, 0, 0, tid, g_xbf, m0, g_bwt, u0);
    load_full(sb, 1, 1, tid, g_xbf, m0, g_bwt, u0);
    load_full(sb, 2, 2, tid, g_xbf, m0, g_bwt, u0);
    #pragma unroll 1
    for (int ci = 0; ci < 32; ci++) {
        if (ci < 30)       CP_WAIT(2);
        else if (ci == 30) CP_WAIT(1);
        else               CP_WAIT(0);
        __syncthreads();
        if (ci + 3 < 32)
            load_full(sb, (ci + 3) & 3, ci + 3, tid, g_xbf, m0, g_bwt, u0);
        compute_chunk(sb, ci & 3, tid, acc);
    }

    int lane = tid & 31, wid = tid >> 5;
    int wr = wid >> 2, wc = wid & 3;
    int r0 = wr * 32 + (lane >> 2);
    int ub = u0 + wc * 16 + (lane & 3);
    #pragma unroll
    for (int mt = 0; mt < 2; mt++)
        #pragma unroll
        for (int h = 0; h < 2; h++) {
            int m = (int)m0 + r0 + mt * 16 + h * 8;
            int bb = m >> 9, t = m & (TLEN - 1);
            size_t base = ((size_t)(t + OV) * BSZ + bb) * UDIM;
            #pragma unroll
            for (int nt = 0; nt < 4; nt++)
                g_W[base + ub + nt * 4] =
                    make_float2(acc[mt][nt][2 * h], acc[mt][nt][2 * h + 1]);
        }
}

// ---------------------------------------------------------------------------
// Grid barrier (128 CTAs co-resident)
// ---------------------------------------------------------------------------
static __device__ __forceinline__ void grid_barrier()
{
    __threadfence();
    __syncthreads();
    if (threadIdx.x == 0) {
        unsigned my = *(volatile unsigned*)&g_bar_phase;
        unsigned rank = atomicAdd(&g_bar_cnt, 1u);
        if (rank == NCTA_SCAN - 1) {
            g_bar_cnt = 0;
            __threadfence();
            *(volatile unsigned*)&g_bar_phase = my + 1u;
        } else {
            while (*(volatile unsigned*)&g_bar_phase == my) __nanosleep(32);
        }
        __threadfence();
    }
    __syncthreads();
}

// ---------------------------------------------------------------------------
// Kernel 2: persistent scan. 44 steps; 128 CTAs = 8 m-tiles x 16 u-tiles.
// Pre-barrier prefetch of step-invariant B-halves + W(s+1); W read via smem.
// ---------------------------------------------------------------------------
__global__ __launch_bounds__(NTHR) void scan_tc(float2* __restrict__ out)
{
    extern __shared__ char smem[];
    uint32_t sb = smem_u32(smem);
    int tid = threadIdx.x;
    size_t m0 = (size_t)(blockIdx.x >> 4) * 128;
    int u0 = (blockIdx.x & 15) * 64;

    int lane = tid & 31, wid = tid >> 5;
    int wr = wid >> 2, wc = wid & 3;
    int r0 = wr * 32 + (lane >> 2);
    int ul = wc * 16 + (lane & 3);   // u - u0

    // Prologue: W(0) into smem, fully drained.
    load_W(sb, 0, tid, m0, u0);
    CP_WAIT(0);
    __syncthreads();

    for (int s = 0; s < NSTEP; s++) {
        float acc[2][4][4];
        #pragma unroll
        for (int a = 0; a < 2; a++)
            #pragma unroll
            for (int b = 0; b < 4; b++)
                #pragma unroll
                for (int c = 0; c < 4; c++) acc[a][b][c] = 0.f;

        if (s != 0)   // s==0: state exactly zero (B0..B2 + W(s) already queued)
            run_gemm(sb, tid, g_z[s & 1], m0, g_awt, u0, acc);

        // Register-direct epilogue; W from smem.
        __half* nz = g_z[(s + 1) & 1];
        #pragma unroll
        for (int mt = 0; mt < 2; mt++)
            #pragma unroll
            for (int h = 0; h < 2; h++) {
                int g = (int)m0 + r0 + mt * 16 + h * 8;
                int c = g >> 6, bb = g & 63;
                int wslot = c * CLEN + s;
                int rloc = r0 + mt * 16 + h * 8;
                size_t zbase = (size_t)g * KREAL;
                #pragma unroll
                for (int nt = 0; nt < 4; nt++) {
                    int u = u0 + ul + nt * 4;
                    float2 w = *(float2*)(smem + WOFF + rloc * WPITCH + (ul + nt * 4) * 8);
                    float zr = acc[mt][nt][2 * h]     + w.x;
                    float zi = acc[mt][nt][2 * h + 1] + w.y;
                    nz[zbase + u]        = __float2half_rn(zr);
                    nz[zbase + u + 1024] = __float2half_rn(zi);
                    if (s >= OV) {
                        int tout = wslot - OV;
                        float r2 = zr * zr + zi * zi;
                        float cc = 2.0f - r2;
                        out[((size_t)bb * TLEN + tout) * UDIM + u] =
                            make_float2(fmaf(-OMEGA_F, zi, cc * zr),
                                        fmaf( OMEGA_F, zr, cc * zi));
                    }
                }
            }

        // Protect W region + stages 0-2 from prefetch until all warps done.
        __syncthreads();

        if (s + 1 < NSTEP) {
            // Pre-barrier prefetch (streams while CTAs spin at the barrier):
            // step-invariant weight halves for chunks 0-2, and W(s+1).
            load_half_B(sb, 0, 0, tid, g_awt, u0);
            load_half_B(sb, 1, 1, tid, g_awt, u0);
            load_half_B(sb, 2, 2, tid, g_awt, u0);
            load_W(sb, s + 1, tid, m0, u0);
        }
        grid_barrier();
    }
}

// ---------------------------------------------------------------------------
// Launch: 4 graph nodes
// ---------------------------------------------------------------------------
extern "C" void kernel_launch(void* const* d_in, const int* in_sizes, int n_in,
                              void* d_out, int out_size)
{
    const float* xr  = (const float*)d_in[0];
    const float* xi  = (const float*)d_in[1];
    const float* Ar  = (const float*)d_in[2];
    const float* Ai  = (const float*)d_in[3];
    const float* Br  = (const float*)d_in[4];
    const float* Bi  = (const float*)d_in[5];
    const float* z0r = (const float*)d_in[6];
    const float* z0i = (const float*)d_in[7];
    float2* out = (float2*)d_out;

    cudaFuncSetAttribute(wgemm_tc, cudaFuncAttributeMaxDynamicSharedMemorySize, SMEM_WG);
    cudaFuncSetAttribute(scan_tc,  cudaFuncAttributeMaxDynamicSharedMemorySize, SMEM_SCAN);

    pack_tc<<<(KREAL * KREAL) / 256, 256>>>(Ar, Ai, Br, Bi, z0r, z0i);
    xhalf<<<(XROWS * KREAL / 4) / 256, 256>>>(xr, xi);
    wgemm_tc<<<dim3(16, 256), NTHR, SMEM_WG>>>();
    scan_tc<<<NCTA_SCAN, NTHR, SMEM_SCAN>>>(out);
}

// round 17
// speedup vs baseline: 1.7065x; 1.0026x over previous
#include <cuda_runtime.h>
#include <cuda_fp16.h>
#include <cstdint>

#define BSZ    64
#define TLEN   512
#define UDIM   1024
#define KREAL  2048
#define XROWS  32768
#define OMEGA_F 0.006135923151542565f
#define OV     12
#define CLEN   32
#define NSTEP  (CLEN + OV)          // 44
#define SROWS  1024
#define NCTA_SCAN 128
#define NGRP   8                    // independent m-tile groups
#define NCTA_GRP 16                 // u-tile CTAs per group (the only sync scope)
#define NTHR   512

// smem: four stages x (A 16K + B 16K) = 128 KB, then W buffer (128 x 528B)
#define TB      16384
#define STB     32768
#define SM_A(st) ((st)*STB)
#define SM_B(st) ((st)*STB + TB)
#define WOFF    131072
#define WPITCH  528
#define SMEM_SCAN (WOFF + 128 * WPITCH)   // 198656
#define SMEM_WG 131072

// ---------------------------------------------------------------------------
// Device scratch (static; no runtime allocation)
// ---------------------------------------------------------------------------
__device__ float2 g_W[(size_t)(TLEN + OV) * BSZ * UDIM];            // fp32 W; slots 0..OV-1 pad (z0 at OV-1)
__device__ __align__(16) __half g_awt[(size_t)KREAL * KREAL];       // A weights [n][k] fp16, x0.5
__device__ __align__(16) __half g_bwt[(size_t)KREAL * KREAL];       // B weights
__device__ __align__(16) __half g_xbf[(size_t)XROWS * KREAL];       // x fp16 [row][k]
__device__ __align__(16) __half g_z[2][(size_t)SROWS * KREAL];      // state double buffer fp16
// Per-group barrier state, one 128B line per group (no cross-group ping-pong).
__device__ unsigned g_bar_cnt[NGRP * 32];
__device__ unsigned g_bar_phase[NGRP * 32];

// ---------------------------------------------------------------------------
// Helpers
// ---------------------------------------------------------------------------
#define SWZ(x) ((x) ^ (((x) >> 3) & 0x70))

static __device__ __forceinline__ uint32_t smem_u32(const void* p) {
    uint32_t a;
    asm("{ .reg .u64 t; cvta.to.shared.u64 t, %1; cvt.u32.u64 %0, t; }" : "=r"(a) : "l"(p));
    return a;
}
#define CP16(saddr, gptr) \
    asm volatile("cp.async.cg.shared.global [%0], [%1], 16;" :: "r"(saddr), "l"(gptr))
#define CP_COMMIT() asm volatile("cp.async.commit_group;" ::: "memory")
#define CP_WAIT(n)  asm volatile("cp.async.wait_group %0;" :: "n"(n) : "memory")

static __device__ __forceinline__ void ldsm_x4(uint32_t (&r)[4], uint32_t a) {
    asm volatile("ldmatrix.sync.aligned.m8n8.x4.shared.b16 {%0,%1,%2,%3}, [%4];"
        : "=r"(r[0]), "=r"(r[1]), "=r"(r[2]), "=r"(r[3]) : "r"(a));
}
static __device__ __forceinline__ void mma_fp16(
    float (&d)[4], const uint32_t (&a)[4], uint32_t b0, uint32_t b1)
{
    asm volatile("mma.sync.aligned.m16n8k16.row.col.f32.f16.f16.f32 "
        "{%0,%1,%2,%3}, {%4,%5,%6,%7}, {%8,%9}, {%0,%1,%2,%3};"
        : "+f"(d[0]), "+f"(d[1]), "+f"(d[2]), "+f"(d[3])
        : "r"(a[0]), "r"(a[1]), "r"(a[2]), "r"(a[3]), "r"(b0), "r"(b1));
}
static __device__ __forceinline__ uint32_t pkh(__half a, __half b) {
    return (uint32_t)__half_as_ushort(a) | ((uint32_t)__half_as_ushort(b) << 16);
}

// ---------------------------------------------------------------------------
// Kernel 0a: pack weights (transposed real embedding, 0.5-scaled, fp16),
//            init W pad (z0 at slot OV-1), zero state buf 0
// ---------------------------------------------------------------------------
__global__ __launch_bounds__(256) void pack_tc(
    const float* __restrict__ Ar, const float* __restrict__ Ai,
    const float* __restrict__ Br, const float* __restrict__ Bi,
    const float* __restrict__ z0r, const float* __restrict__ z0i)
{
    int i = blockIdx.x * 256 + threadIdx.x;   // 0 .. 4M-1
    {
        int n = i >> 11, k = i & 2047;
        int kk = k & 1023, nn = n & 1023;
        float a, b;
        if (k < 1024) {
            if (n < 1024) { a = Ar[k*1024 + n];  b = Br[k*1024 + n];  }
            else          { a = Ai[k*1024 + nn]; b = Bi[k*1024 + nn]; }
        } else {
            if (n < 1024) { a = -Ai[kk*1024 + n];  b = -Bi[kk*1024 + n];  }
            else          { a =  Ar[kk*1024 + nn]; b =  Br[kk*1024 + nn]; }
        }
        g_awt[i] = __float2half_rn(0.5f * a);
        g_bwt[i] = __float2half_rn(0.5f * b);
    }
    if (i < OV * BSZ * UDIM) {                // W pad, z0 at slot OV-1
        int slot = i >> 16, r = i & 65535;
        g_W[i] = (slot == OV - 1) ? make_float2(z0r[r], z0i[r]) : make_float2(0.f, 0.f);
    }
    if (i < (int)(SROWS * KREAL / 2))          // 1.05M u32 = state buf 0
        ((uint32_t*)g_z[0])[i] = 0u;
}

// ---------------------------------------------------------------------------
// Kernel 0b: convert x to fp16, k-layout [re(1024) | im(1024)]
// ---------------------------------------------------------------------------
__global__ __launch_bounds__(256) void xhalf(
    const float* __restrict__ xr, const float* __restrict__ xi)
{
    int i = blockIdx.x * 256 + threadIdx.x;
    int row = i >> 9;
    int kq = (i & 511) * 4;
    const float* src = (kq < 1024) ? xr : xi;
    float4 v = *(const float4*)(src + (size_t)row * 1024 + (kq & 1023));
    *(uint2*)(g_xbf + (size_t)row * KREAL + kq) = make_uint2(
        pkh(__float2half_rn(v.x), __float2half_rn(v.y)),
        pkh(__float2half_rn(v.z), __float2half_rn(v.w)));
}

// ---------------------------------------------------------------------------
// GEMM machinery.  512 threads, warp grid 4x4 (each warp 32 rows x 32 cols).
//   A: activations fp16 [row][2048], rows arow0..+127, K chunks of 64
//   B: weights fp16 [n][2048]; INTERLEAVED smem rows:
//       j even -> n = u0 + j/2        (re weight row)
//       j odd  -> n = 1024 + u0 + j/2 (im weight row)
//   => mma output cols (2u', 2u'+1) = (re, im) of u = u0 + u' in ONE thread.
// ---------------------------------------------------------------------------
static __device__ __forceinline__ void load_half_A(
    uint32_t sb, int st, int ci, int tid, const __half* a, size_t arow0)
{
    #pragma unroll
    for (int l = 0; l < 2; l++) {
        int idx = tid + l * NTHR;
        int row = idx >> 3, g16 = idx & 7;
        CP16(sb + SM_A(st) + SWZ(row * 128 + g16 * 16),
             a + (arow0 + row) * KREAL + ci * 64 + g16 * 8);
    }
    CP_COMMIT();
}
static __device__ __forceinline__ void load_half_B(
    uint32_t sb, int st, int ci, int tid, const __half* w, int u0)
{
    #pragma unroll
    for (int l = 0; l < 2; l++) {
        int idx = tid + l * NTHR;
        int j = idx >> 3, g16 = idx & 7;
        int n = u0 + (j >> 1) + ((j & 1) ? 1024 : 0);
        CP16(sb + SM_B(st) + SWZ(j * 128 + g16 * 16),
             w + (size_t)n * KREAL + ci * 64 + g16 * 8);
    }
    CP_COMMIT();
}
static __device__ __forceinline__ void load_full(
    uint32_t sb, int st, int ci, int tid,
    const __half* a, size_t arow0, const __half* w, int u0)
{
    #pragma unroll
    for (int l = 0; l < 2; l++) {
        int idx = tid + l * NTHR;
        int row = idx >> 3, g16 = idx & 7;
        CP16(sb + SM_A(st) + SWZ(row * 128 + g16 * 16),
             a + (arow0 + row) * KREAL + ci * 64 + g16 * 8);
    }
    #pragma unroll
    for (int l = 0; l < 2; l++) {
        int idx = tid + l * NTHR;
        int j = idx >> 3, g16 = idx & 7;
        int n = u0 + (j >> 1) + ((j & 1) ? 1024 : 0);
        CP16(sb + SM_B(st) + SWZ(j * 128 + g16 * 16),
             w + (size_t)n * KREAL + ci * 64 + g16 * 8);
    }
    CP_COMMIT();
}
// Cooperative W(s) prefetch into padded smem (one group; 4096 x 16B).
static __device__ __forceinline__ void load_W(
    uint32_t sb, int s, int tid, size_t m0, int u0)
{
    #pragma unroll
    for (int l = 0; l < 8; l++) {
        int idx = tid + l * NTHR;            // 0..4095
        int row = idx >> 5, c16 = idx & 31;
        int g = (int)m0 + row;
        int c = g >> 6, bb = g & 63;
        int wslot = c * CLEN + s;
        const float2* src = g_W + (size_t)(wslot * BSZ + bb) * UDIM + u0 + c16 * 2;
        CP16(sb + WOFF + row * WPITCH + c16 * 16, src);
    }
    CP_COMMIT();
}

static __device__ __forceinline__ void compute_chunk(
    uint32_t sb, int st, int tid, float (&acc)[2][4][4])
{
    int lane = tid & 31, wid = tid >> 5;
    int wr = wid >> 2, wc = wid & 3;
    uint32_t abase = sb + SM_A(st);
    uint32_t bbase = sb + SM_B(st);
    int ar = lane & 15, ac = lane >> 4;
    int br = lane & 7, bc = (lane >> 3) & 1, bt = lane >> 4;

    #pragma unroll
    for (int k16 = 0; k16 < 4; k16++) {
        int kb = k16 * 32;
        uint32_t ah[2][4], bh[2][4];
        #pragma unroll
        for (int mt = 0; mt < 2; mt++) {
            uint32_t off = SWZ((wr * 32 + mt * 16 + ar) * 128 + kb + ac * 16);
            ldsm_x4(ah[mt], abase + off);
        }
        #pragma unroll
        for (int np = 0; np < 2; np++) {
            uint32_t off = SWZ((wc * 32 + np * 16 + bt * 8 + br) * 128 + kb + bc * 16);
            ldsm_x4(bh[np], bbase + off);
        }
        #pragma unroll
        for (int mt = 0; mt < 2; mt++)
            #pragma unroll
            for (int nt = 0; nt < 4; nt++) {
                uint32_t b0 = bh[nt >> 1][(nt & 1) * 2], b1 = bh[nt >> 1][(nt & 1) * 2 + 1];
                mma_fp16(acc[mt][nt], ah[mt], b0, b1);
            }
    }
}

// Mainloop for one step.  Entry queue (in order): [B0,B1,B2,W(s)] from the
// pre-barrier prefetch, then [A0,A1,A2] issued here.  wait(2) at ci=0
// completes B0..A0; A1 by ci=1; A2 by ci=2; steady state thereafter.
static __device__ __forceinline__ void run_gemm(
    uint32_t sb, int tid,
    const __half* a, size_t arow0, const __half* w, int u0,
    float (&acc)[2][4][4])
{
    load_half_A(sb, 0, 0, tid, a, arow0);
    load_half_A(sb, 1, 1, tid, a, arow0);
    load_half_A(sb, 2, 2, tid, a, arow0);
    #pragma unroll 1
    for (int ci = 0; ci < 32; ci++) {
        if (ci < 30)       CP_WAIT(2);
        else if (ci == 30) CP_WAIT(1);
        else               CP_WAIT(0);
        __syncthreads();
        if (ci + 3 < 32)
            load_full(sb, (ci + 3) & 3, ci + 3, tid, a, arow0, w, u0);
        compute_chunk(sb, ci & 3, tid, acc);
    }
}

// ---------------------------------------------------------------------------
// Kernel 1: W GEMM.  grid (16 u-tiles, 256 m-tiles), 512 threads.
// ---------------------------------------------------------------------------
__global__ __launch_bounds__(NTHR) void wgemm_tc()
{
    extern __shared__ char smem[];
    uint32_t sb = smem_u32(smem);
    int tid = threadIdx.x;
    size_t m0 = (size_t)blockIdx.y * 128;
    int u0 = blockIdx.x * 64;

    float acc[2][4][4];
    #pragma unroll
    for (int a = 0; a < 2; a++)
        #pragma unroll
        for (int b = 0; b < 4; b++)
            #pragma unroll
            for (int c = 0; c < 4; c++) acc[a][b][c] = 0.f;

    load_full(sb, 0, 0, tid, g_xbf, m0, g_bwt, u0);
    load_full(sb, 1, 1, tid, g_xbf, m0, g_bwt, u0);
    load_full(sb, 2, 2, tid, g_xbf, m0, g_bwt, u0);
    #pragma unroll 1
    for (int ci = 0; ci < 32; ci++) {
        if (ci < 30)       CP_WAIT(2);
        else if (ci == 30) CP_WAIT(1);
        else               CP_WAIT(0);
        __syncthreads();
        if (ci + 3 < 32)
            load_full(sb, (ci + 3) & 3, ci + 3, tid, g_xbf, m0, g_bwt, u0);
        compute_chunk(sb, ci & 3, tid, acc);
    }

    int lane = tid & 31, wid = tid >> 5;
    int wr = wid >> 2, wc = wid & 3;
    int r0 = wr * 32 + (lane >> 2);
    int ub = u0 + wc * 16 + (lane & 3);
    #pragma unroll
    for (int mt = 0; mt < 2; mt++)
        #pragma unroll
        for (int h = 0; h < 2; h++) {
            int m = (int)m0 + r0 + mt * 16 + h * 8;
            int bb = m >> 9, t = m & (TLEN - 1);
            size_t base = ((size_t)(t + OV) * BSZ + bb) * UDIM;
            #pragma unroll
            for (int nt = 0; nt < 4; nt++)
                g_W[base + ub + nt * 4] =
                    make_float2(acc[mt][nt][2 * h], acc[mt][nt][2 * h + 1]);
        }
}

// ---------------------------------------------------------------------------
// Per-group barrier: syncs only the 16 u-tile CTAs sharing one m-tile.
// Groups are fully independent row-chains and may drift freely.
// ---------------------------------------------------------------------------
static __device__ __forceinline__ void group_barrier(int grp)
{
    __threadfence();
    __syncthreads();
    if (threadIdx.x == 0) {
        volatile unsigned* ph = &g_bar_phase[grp * 32];
        unsigned my = *ph;
        unsigned rank = atomicAdd(&g_bar_cnt[grp * 32], 1u);
        if (rank == NCTA_GRP - 1) {
            g_bar_cnt[grp * 32] = 0;
            __threadfence();
            *ph = my + 1u;
        } else {
            while (*ph == my) __nanosleep(32);
        }
        __threadfence();
    }
    __syncthreads();
}

// ---------------------------------------------------------------------------
// Kernel 2: persistent scan. 44 steps; 128 CTAs = 8 m-tiles x 16 u-tiles.
// Group-local barrier; pre-barrier prefetch of B-halves + W(s+1).
// ---------------------------------------------------------------------------
__global__ __launch_bounds__(NTHR) void scan_tc(float2* __restrict__ out)
{
    extern __shared__ char smem[];
    uint32_t sb = smem_u32(smem);
    int tid = threadIdx.x;
    int grp = blockIdx.x >> 4;
    size_t m0 = (size_t)grp * 128;
    int u0 = (blockIdx.x & 15) * 64;

    int lane = tid & 31, wid = tid >> 5;
    int wr = wid >> 2, wc = wid & 3;
    int r0 = wr * 32 + (lane >> 2);
    int ul = wc * 16 + (lane & 3);   // u - u0

    // Prologue: W(0) into smem, fully drained.
    load_W(sb, 0, tid, m0, u0);
    CP_WAIT(0);
    __syncthreads();

    for (int s = 0; s < NSTEP; s++) {
        float acc[2][4][4];
        #pragma unroll
        for (int a = 0; a < 2; a++)
            #pragma unroll
            for (int b = 0; b < 4; b++)
                #pragma unroll
                for (int c = 0; c < 4; c++) acc[a][b][c] = 0.f;

        if (s != 0)   // s==0: state exactly zero (B0..B2 + W(s) already queued)
            run_gemm(sb, tid, g_z[s & 1], m0, g_awt, u0, acc);

        // Register-direct epilogue; W from smem.
        __half* nz = g_z[(s + 1) & 1];
        #pragma unroll
        for (int mt = 0; mt < 2; mt++)
            #pragma unroll
            for (int h = 0; h < 2; h++) {
                int g = (int)m0 + r0 + mt * 16 + h * 8;
                int c = g >> 6, bb = g & 63;
                int wslot = c * CLEN + s;
                int rloc = r0 + mt * 16 + h * 8;
                size_t zbase = (size_t)g * KREAL;
                #pragma unroll
                for (int nt = 0; nt < 4; nt++) {
                    int u = u0 + ul + nt * 4;
                    float2 w = *(float2*)(smem + WOFF + rloc * WPITCH + (ul + nt * 4) * 8);
                    float zr = acc[mt][nt][2 * h]     + w.x;
                    float zi = acc[mt][nt][2 * h + 1] + w.y;
                    nz[zbase + u]        = __float2half_rn(zr);
                    nz[zbase + u + 1024] = __float2half_rn(zi);
                    if (s >= OV) {
                        int tout = wslot - OV;
                        float r2 = zr * zr + zi * zi;
                        float cc = 2.0f - r2;
                        out[((size_t)bb * TLEN + tout) * UDIM + u] =
                            make_float2(fmaf(-OMEGA_F, zi, cc * zr),
                                        fmaf( OMEGA_F, zr, cc * zi));
                    }
                }
            }

        // Protect W region + stages 0-2 from prefetch until all warps done.
        __syncthreads();

        if (s + 1 < NSTEP) {
            // Pre-barrier prefetch (streams while CTAs wait at the group barrier):
            // step-invariant weight halves for chunks 0-2, and W(s+1).
            load_half_B(sb, 0, 0, tid, g_awt, u0);
            load_half_B(sb, 1, 1, tid, g_awt, u0);
            load_half_B(sb, 2, 2, tid, g_awt, u0);
            load_W(sb, s + 1, tid, m0, u0);
        }
        group_barrier(grp);
    }
}

// ---------------------------------------------------------------------------
// Launch: 4 graph nodes
// ---------------------------------------------------------------------------
extern "C" void kernel_launch(void* const* d_in, const int* in_sizes, int n_in,
                              void* d_out, int out_size)
{
    const float* xr  = (const float*)d_in[0];
    const float* xi  = (const float*)d_in[1];
    const float* Ar  = (const float*)d_in[2];
    const float* Ai  = (const float*)d_in[3];
    const float* Br  = (const float*)d_in[4];
    const float* Bi  = (const float*)d_in[5];
    const float* z0r = (const float*)d_in[6];
    const float* z0i = (const float*)d_in[7];
    float2* out = (float2*)d_out;

    cudaFuncSetAttribute(wgemm_tc, cudaFuncAttributeMaxDynamicSharedMemorySize, SMEM_WG);
    cudaFuncSetAttribute(scan_tc,  cudaFuncAttributeMaxDynamicSharedMemorySize, SMEM_SCAN);

    pack_tc<<<(KREAL * KREAL) / 256, 256>>>(Ar, Ai, Br, Bi, z0r, z0i);
    xhalf<<<(XROWS * KREAL / 4) / 256, 256>>>(xr, xi);
    wgemm_tc<<<dim3(16, 256), NTHR, SMEM_WG>>>();
    scan_tc<<<NCTA_SCAN, NTHR, SMEM_SCAN>>>(out);
}